// round 15
// baseline (speedup 1.0000x reference)
#include <cuda_runtime.h>
#include <cuda_fp16.h>
#include <mma.h>
#include <cstdint>

using namespace nvcuda;

// ---------------- problem constants ----------------
constexpr int T_      = 2048;
constexpr int DIM_    = 2048;
constexpr int INTER_  = 1408;
constexpr int SINTER_ = 2816;          // == 2 * INTER_
constexpr int NE_     = 16;
constexpr int NE2     = 18;            // 16 routed + 2 shared pseudo-experts
constexpr int TOPK_   = 6;
constexpr int NSLOT   = 8;             // 6 routed + 2 shared
constexpr int NPAIR   = T_ * TOPK_;    // 12288

// ---------------- tiling ----------------
constexpr int BM     = 128;
constexpr int BN_UP  = 128;
constexpr int BND    = 128;
constexpr int BK     = 64;             // K per stage (4 mma k-steps of 16)
constexpr int STAGES = 3;
constexpr int BKP    = BK    + 8;      // 72 halves
constexpr int BNPU   = BN_UP + 8;      // 136 halves
constexpr int BNDP   = BND   + 8;      // 136 halves
constexpr int HROWS  = NPAIR + NE_ * BM + 2 * T_;   // 18,432 padded rows

constexpr int UP_PIPE_B   = STAGES * (BM * BKP + 2 * BK * BNPU) * 2;  // 159,744
constexpr int UP_FUSE_B   = 2 * BM * 132 * 4;                         // 135,168
constexpr int UP_SMEM_B   = (UP_PIPE_B > UP_FUSE_B) ? UP_PIPE_B : UP_FUSE_B;
constexpr int DOWN_SMEM_B = STAGES * (BM * BKP + BK * BNDP) * 2;      // 107,520
constexpr int FP_ST       = 132;

// ---------------- device scratch (static, no allocation) ----------------
__device__ int    g_is64;
__device__ int    g_cnt[NE2];
__device__ int    g_offpad[NE2 + 1];
__device__ int    g_list[NE_ * NPAIR];
__device__ __half g_W1h [(size_t)NE_ * DIM_ * INTER_];
__device__ __half g_W3h [(size_t)NE_ * DIM_ * INTER_];
__device__ __half g_W2h [(size_t)NE_ * INTER_ * DIM_];
__device__ __half g_Ws1h[(size_t)DIM_ * SINTER_];
__device__ __half g_Ws3h[(size_t)DIM_ * SINTER_];
__device__ __half g_Ws2h[(size_t)SINTER_ * DIM_];
__device__ __half g_Xh  [(size_t)T_ * DIM_];
__device__ __half g_Hh  [(size_t)HROWS * INTER_];
__device__ float  g_Yb  [(size_t)T_ * NSLOT * DIM_];

// ---------------- cp.async helpers ----------------
__device__ __forceinline__ void cpa16(__half* smem, const __half* g) {
    unsigned saddr = (unsigned)__cvta_generic_to_shared(smem);
    asm volatile("cp.async.cg.shared.global [%0], [%1], 16;" :: "r"(saddr), "l"(g));
}
#define CP_COMMIT()  asm volatile("cp.async.commit_group;")
#define CP_WAIT(n)   asm volatile("cp.async.wait_group %0;" :: "n"(n))

// ---------------- fp32 -> fp16 conversion prepass ----------------
__global__ void __launch_bounds__(256, 4) cvt_kernel(const float* __restrict__ s,
                                                     __half* __restrict__ d, int n) {
    int i = (blockIdx.x * 256 + threadIdx.x) * 8;
    if (i >= n) return;
    float4 a = *(const float4*)(s + i);
    float4 b = *(const float4*)(s + i + 4);
    __half2 h0 = __floats2half2_rn(a.x, a.y), h1 = __floats2half2_rn(a.z, a.w);
    __half2 h2 = __floats2half2_rn(b.x, b.y), h3 = __floats2half2_rn(b.z, b.w);
    uint4 o;
    o.x = *reinterpret_cast<unsigned*>(&h0);
    o.y = *reinterpret_cast<unsigned*>(&h1);
    o.z = *reinterpret_cast<unsigned*>(&h2);
    o.w = *reinterpret_cast<unsigned*>(&h3);
    *reinterpret_cast<uint4*>(d + i) = o;
}

// ---------------- dtype probe (int64 vs int32 indices) ----------------
__global__ void detect_kernel(const int* __restrict__ idx32) {
    if (threadIdx.x == 0) {
        int a = 0;
        #pragma unroll 1
        for (int i = 0; i < 128; i++) a |= idx32[2 * i + 1];
        g_is64 = (a == 0) ? 1 : 0;
    }
}

// ---------------- deterministic per-expert pair lists ----------------
__global__ void build_lists(const int* __restrict__ idx32) {
    const int e = blockIdx.x;
    const bool is64 = (g_is64 != 0);
    __shared__ int wsum[8];
    __shared__ int sbase;
    const int tid = threadIdx.x, lane = tid & 31, w = tid >> 5;
    if (tid == 0) sbase = 0;
    __syncthreads();
    for (int st = 0; st < NPAIR; st += 256) {
        int p = st + tid;
        int v = is64 ? idx32[2 * p] : idx32[p];
        bool m = (v == e);
        unsigned bal = __ballot_sync(0xffffffffu, m);
        int within = __popc(bal & ((1u << lane) - 1u));
        if (lane == 0) wsum[w] = __popc(bal);
        __syncthreads();
        int off = sbase;
        for (int i = 0; i < w; i++) off += wsum[i];
        if (m) g_list[e * NPAIR + off + within] = p;
        __syncthreads();
        if (tid == 0) {
            int tot = 0;
            for (int i = 0; i < 8; i++) tot += wsum[i];
            sbase += tot;
        }
        __syncthreads();
    }
    if (tid == 0) g_cnt[e] = sbase;
}

__global__ void prefix_kernel() {
    if (threadIdx.x == 0) {
        g_cnt[16] = T_;
        g_cnt[17] = T_;
        int off = 0;
        for (int e = 0; e < NE2; e++) {
            g_offpad[e] = off;
            off += ((g_cnt[e] + BM - 1) / BM) * BM;
        }
        g_offpad[NE2] = off;
    }
}

// ---------------- wmma types (fp16 in, fp32 accum) ----------------
typedef wmma::fragment<wmma::matrix_a, 16, 16, 16, __half, wmma::row_major> FA;
typedef wmma::fragment<wmma::matrix_b, 16, 16, 16, __half, wmma::row_major> FB;
typedef wmma::fragment<wmma::accumulator, 16, 16, 16, float> FC;

// =====================================================================
// up kernel: H[rows] = silu(A@B1) * (A@B3).  256 threads, 8 warps.
// e < 16:  routed expert, A rows gathered via g_list, B = W1/W3[e].
// e >= 16: shared pseudo-expert h=e-16, B = Ws1/Ws3 column slice, ldB=SINTER.
// =====================================================================
__global__ void __launch_bounds__(256, 1)
up_kernel()
{
    constexpr int KT = DIM_ / BK;     // 32
    const int e = blockIdx.z;
    const int cnt = g_cnt[e];
    if ((int)blockIdx.y * BM >= cnt) return;
    const int hbase = g_offpad[e] + blockIdx.y * BM;
    const bool routed = (e < NE_);

    const __half* B1;
    const __half* B3;
    size_t ldB;
    if (routed) {
        B1 = g_W1h + (size_t)e * DIM_ * INTER_;
        B3 = g_W3h + (size_t)e * DIM_ * INTER_;
        ldB = INTER_;
    } else {
        B1 = g_Ws1h + (size_t)(e - NE_) * INTER_;
        B3 = g_Ws3h + (size_t)(e - NE_) * INTER_;
        ldB = SINTER_;
    }
    const int n0 = blockIdx.x * BN_UP;

    extern __shared__ __half sm[];
    __half* sA  = sm;                                  // [S][BM][BKP]
    __half* sB1 = sm + STAGES * BM * BKP;              // [S][BK][BNPU]
    __half* sB3 = sB1 + STAGES * BK * BNPU;

    const int tid  = threadIdx.x;
    const int warp = tid >> 5;
    const int grp  = warp >> 2;        // 0: W1, 1: W3
    const int wl   = warp & 3;
    const int wm   = wl & 1;           // 2 warps in M (64 rows)
    const int wn   = wl >> 1;          // 2 warps in N (64 cols)

    // A: 128x64 halves = 1024 chunks of 8; 4 per thread (id = tid + 256*i)
    int tokA[4];
    #pragma unroll
    for (int i = 0; i < 4; i++) {
        int id  = tid + 256 * i;
        int r   = id >> 3;
        int row = blockIdx.y * BM + r;
        if (routed) tokA[i] = (row < cnt) ? (g_list[e * NPAIR + row] / TOPK_) : 0;
        else        tokA[i] = (row < cnt) ? row : 0;
    }
    // B: per matrix 64x128 halves = 1024 chunks; threads 0-127 -> B1,
    // 128-255 -> B3, 8 chunks each (id = (tid&127) + 128*i)
    const int bmat = tid >> 7;
    const __half* bsrcM = bmat ? B3 : B1;
    __half* bdst = bmat ? sB3 : sB1;

    auto copy_stage = [&](int kt, int st) {
        const int k0 = kt * BK;
        #pragma unroll
        for (int i = 0; i < 4; i++) {
            int id = tid + 256 * i;
            int r  = id >> 3;
            int c8 = (id & 7) * 8;
            cpa16(&sA[st * BM * BKP + r * BKP + c8],
                  g_Xh + (size_t)tokA[i] * DIM_ + k0 + c8);
        }
        #pragma unroll
        for (int i = 0; i < 8; i++) {
            int id = (tid & 127) + 128 * i;
            int r  = id >> 4;
            int c8 = (id & 15) * 8;
            cpa16(&bdst[st * BK * BNPU + r * BNPU + c8],
                  bsrcM + (size_t)(k0 + r) * ldB + n0 + c8);
        }
    };

    FC acc[4][4];
    #pragma unroll
    for (int mi = 0; mi < 4; mi++)
        #pragma unroll
        for (int ni = 0; ni < 4; ni++) wmma::fill_fragment(acc[mi][ni], 0.f);

    const __half* sBg = grp ? sB3 : sB1;

    #pragma unroll
    for (int s = 0; s < STAGES - 1; s++) { copy_stage(s, s); CP_COMMIT(); }

    for (int kt = 0; kt < KT; kt++) {
        CP_WAIT(STAGES - 2);
        __syncthreads();
        int nk = kt + STAGES - 1;
        if (nk < KT) copy_stage(nk, nk % STAGES);
        CP_COMMIT();
        const int st = kt % STAGES;
        #pragma unroll
        for (int kk = 0; kk < BK; kk += 16) {
            FA fa[4];
            FB fb[4];
            #pragma unroll
            for (int mi = 0; mi < 4; mi++)
                wmma::load_matrix_sync(fa[mi], &sA[(st * BM + wm * 64 + mi * 16) * BKP + kk], BKP);
            #pragma unroll
            for (int ni = 0; ni < 4; ni++)
                wmma::load_matrix_sync(fb[ni], &sBg[(st * BK + kk) * BNPU + wn * 64 + ni * 16], BNPU);
            #pragma unroll
            for (int mi = 0; mi < 4; mi++)
                #pragma unroll
                for (int ni = 0; ni < 4; ni++)
                    wmma::mma_sync(acc[mi][ni], fa[mi], fb[ni], acc[mi][ni]);
        }
    }

    // ---- epilogue: dump both groups' accs to smem floats, fuse, store fp16 H
    CP_WAIT(0);
    __syncthreads();
    float* sF  = (float*)sm;                  // [2][BM][FP_ST]
    float* sFm = sF + grp * (BM * FP_ST);
    #pragma unroll
    for (int mi = 0; mi < 4; mi++)
        #pragma unroll
        for (int ni = 0; ni < 4; ni++)
            wmma::store_matrix_sync(&sFm[(wm * 64 + mi * 16) * FP_ST + wn * 64 + ni * 16],
                                    acc[mi][ni], FP_ST, wmma::mem_row_major);
    __syncthreads();

    {
        const int row = tid >> 1;
        const int seg = (tid & 1) * 64;
        const float* p1 = &sF[row * FP_ST + seg];
        const float* p3 = p1 + BM * FP_ST;
        __half* dst = g_Hh + (size_t)(hbase + row) * INTER_ + n0 + seg;
        #pragma unroll
        for (int c = 0; c < 64; c += 16) {
            __align__(16) __half hbuf[16];
            #pragma unroll
            for (int j = 0; j < 16; j++) {
                float u = p1[c + j];
                float s = u / (1.f + __expf(-u));
                hbuf[j] = __float2half_rn(s * p3[c + j]);
            }
            *(uint4*)(dst + c)     = *(uint4*)(hbuf);
            *(uint4*)(dst + c + 8) = *(uint4*)(hbuf + 8);
        }
    }
}

// =====================================================================
// down kernel: Y = H @ B.  128 threads, 4 warps (2x2 of 64x64), 2 CTAs/SM.
// K = INTER_ uniformly.  e<16: scatter to slot t*8+k scaled by routing
// weight.  e>=16: B = Ws2 rows [h*INTER,(h+1)*INTER), slot t*8+6+h, w=1.
// =====================================================================
__global__ void __launch_bounds__(128, 2)
down_kernel(const float* __restrict__ wts)
{
    constexpr int KT = INTER_ / BK;   // 22
    const int e = blockIdx.z;
    const int cnt = g_cnt[e];
    if ((int)blockIdx.y * BM >= cnt) return;
    const int abase = g_offpad[e] + blockIdx.y * BM;
    const bool routed = (e < NE_);

    const __half* Bh = routed ? (g_W2h + (size_t)e * INTER_ * DIM_)
                              : (g_Ws2h + (size_t)(e - NE_) * INTER_ * DIM_);
    const int n0 = blockIdx.x * BND;

    extern __shared__ __half sm[];
    __half* sA = sm;                                // [S][BM][BKP]
    __half* sB = sm + STAGES * BM * BKP;            // [S][BK][BNDP]

    const int tid  = threadIdx.x;
    const int warp = tid >> 5;
    const int wm   = warp & 1;
    const int wn   = warp >> 1;

    auto copy_stage = [&](int kt, int st) {
        const int k0 = kt * BK;
        #pragma unroll
        for (int i = 0; i < 8; i++) {
            int id = tid + 128 * i;
            int r  = id >> 3;
            int c8 = (id & 7) * 8;
            cpa16(&sA[st * BM * BKP + r * BKP + c8],
                  g_Hh + (size_t)(abase + r) * INTER_ + k0 + c8);
        }
        #pragma unroll
        for (int i = 0; i < 8; i++) {
            int id = tid + 128 * i;
            int r  = id >> 4;
            int c8 = (id & 15) * 8;
            cpa16(&sB[st * BK * BNDP + r * BNDP + c8],
                  Bh + (size_t)(k0 + r) * DIM_ + n0 + c8);
        }
    };

    FC acc[4][4];
    #pragma unroll
    for (int mi = 0; mi < 4; mi++)
        #pragma unroll
        for (int ni = 0; ni < 4; ni++) wmma::fill_fragment(acc[mi][ni], 0.f);

    #pragma unroll
    for (int s = 0; s < STAGES - 1; s++) { copy_stage(s, s); CP_COMMIT(); }

    for (int kt = 0; kt < KT; kt++) {
        CP_WAIT(STAGES - 2);
        __syncthreads();
        int nk = kt + STAGES - 1;
        if (nk < KT) copy_stage(nk, nk % STAGES);
        CP_COMMIT();
        const int st = kt % STAGES;
        #pragma unroll
        for (int kk = 0; kk < BK; kk += 16) {
            FA fa[4];
            FB fb[4];
            #pragma unroll
            for (int mi = 0; mi < 4; mi++)
                wmma::load_matrix_sync(fa[mi], &sA[(st * BM + wm * 64 + mi * 16) * BKP + kk], BKP);
            #pragma unroll
            for (int ni = 0; ni < 4; ni++)
                wmma::load_matrix_sync(fb[ni], &sB[(st * BK + kk) * BNDP + wn * 64 + ni * 16], BNDP);
            #pragma unroll
            for (int mi = 0; mi < 4; mi++)
                #pragma unroll
                for (int ni = 0; ni < 4; ni++)
                    wmma::mma_sync(acc[mi][ni], fa[mi], fb[ni], acc[mi][ni]);
        }
    }

    CP_WAIT(0);
    __syncthreads();
    float* sF = (float*)sm;                   // [BM][FP_ST]
    #pragma unroll
    for (int mi = 0; mi < 4; mi++)
        #pragma unroll
        for (int ni = 0; ni < 4; ni++)
            wmma::store_matrix_sync(&sF[(wm * 64 + mi * 16) * FP_ST + wn * 64 + ni * 16],
                                    acc[mi][ni], FP_ST, wmma::mem_row_major);
    __syncthreads();

    {
        const int row = tid;                  // one row per thread
        const float* src = &sF[row * FP_ST];
        const int gslot = blockIdx.y * BM + row;
        if (gslot < cnt) {
            int slot;
            float w;
            if (routed) {
                int p = g_list[e * NPAIR + gslot];
                int t = p / TOPK_;
                int k = p - t * TOPK_;
                slot = t * NSLOT + k;
                w = wts[p];
            } else {
                slot = gslot * NSLOT + TOPK_ + (e - NE_);
                w = 1.f;
            }
            float* dst = g_Yb + (size_t)slot * DIM_ + n0;
            #pragma unroll
            for (int j = 0; j < 128; j += 4) {
                float4 v = *(const float4*)(src + j);
                v.x *= w; v.y *= w; v.z *= w; v.w *= w;
                *(float4*)(dst + j) = v;
            }
        }
    }
}

// ---------------- final reduction: out[t] = sum over 8 slots ----------------
__global__ void __launch_bounds__(256, 1) reduce_kernel(float* __restrict__ out) {
    int i = blockIdx.x * 256 + threadIdx.x;
    const int row4 = DIM_ / 4;
    int t  = i / row4;
    int c4 = i % row4;
    const float* base = g_Yb + (size_t)t * NSLOT * DIM_ + c4 * 4;
    float4 a = *(const float4*)(base);
    #pragma unroll
    for (int k = 1; k < NSLOT; k++) {
        const float4 v = *(const float4*)(base + (size_t)k * DIM_);
        a.x += v.x; a.y += v.y; a.z += v.z; a.w += v.w;
    }
    ((float4*)out)[i] = a;
}

// ---------------- launch (single stream; no stream/event objects) ----------------
extern "C" void kernel_launch(void* const* d_in, const int* in_sizes, int n_in,
                              void* d_out, int out_size) {
    const float* x   = (const float*)d_in[0];
    const float* wts = (const float*)d_in[1];
    const int*   idx = (const int*)  d_in[2];
    const float* W1  = (const float*)d_in[3];
    const float* W3  = (const float*)d_in[4];
    const float* W2  = (const float*)d_in[5];
    const float* Ws1 = (const float*)d_in[6];
    const float* Ws3 = (const float*)d_in[7];
    const float* Ws2 = (const float*)d_in[8];
    float* out = (float*)d_out;

    cudaFuncSetAttribute(up_kernel,   cudaFuncAttributeMaxDynamicSharedMemorySize, UP_SMEM_B);
    cudaFuncSetAttribute(down_kernel, cudaFuncAttributeMaxDynamicSharedMemorySize, DOWN_SMEM_B);

    void *pW1h, *pW3h, *pW2h, *pWs1h, *pWs3h, *pWs2h, *pXh;
    cudaGetSymbolAddress(&pW1h,  g_W1h);
    cudaGetSymbolAddress(&pW3h,  g_W3h);
    cudaGetSymbolAddress(&pW2h,  g_W2h);
    cudaGetSymbolAddress(&pWs1h, g_Ws1h);
    cudaGetSymbolAddress(&pWs3h, g_Ws3h);
    cudaGetSymbolAddress(&pWs2h, g_Ws2h);
    cudaGetSymbolAddress(&pXh,   g_Xh);

    auto cvt = [&](const float* s, void* d, long long n) {
        int blocks = (int)((n + 2047) / 2048);
        cvt_kernel<<<blocks, 256>>>(s, (__half*)d, (int)n);
    };
    const long long nW  = (long long)NE_ * DIM_ * INTER_;
    const long long nWs = (long long)DIM_ * SINTER_;
    cvt(x,   pXh,   (long long)T_ * DIM_);
    cvt(W1,  pW1h,  nW);
    cvt(W3,  pW3h,  nW);
    cvt(Ws1, pWs1h, nWs);
    cvt(Ws3, pWs3h, nWs);
    cvt(W2,  pW2h,  nW);
    cvt(Ws2, pWs2h, nWs);

    detect_kernel<<<1, 32>>>(idx);
    build_lists<<<NE_, 256>>>(idx);
    prefix_kernel<<<1, 32>>>();

    // unified up: routed experts (z<16) + shared pseudo-experts (z=16,17)
    up_kernel<<<dim3(INTER_ / BN_UP, NPAIR / BM, NE2), 256, UP_SMEM_B>>>();
    // unified down: K = INTER for all
    down_kernel<<<dim3(DIM_ / BND, NPAIR / BM, NE2), 128, DOWN_SMEM_B>>>(wts);
    // out[t] = sum over 8 slots
    reduce_kernel<<<(T_ * DIM_ / 4) / 256, 256>>>(out);
}

// round 16
// speedup vs baseline: 1.0200x; 1.0200x over previous
#include <cuda_runtime.h>
#include <cuda_fp16.h>
#include <mma.h>
#include <cstdint>

using namespace nvcuda;

// ---------------- problem constants ----------------
constexpr int T_      = 2048;
constexpr int DIM_    = 2048;
constexpr int INTER_  = 1408;
constexpr int SINTER_ = 2816;          // == 2 * INTER_
constexpr int NE_     = 16;
constexpr int NE2     = 18;            // 16 routed + 2 shared pseudo-experts
constexpr int TOPK_   = 6;
constexpr int NSLOT   = 8;             // 6 routed + 2 shared
constexpr int NPAIR   = T_ * TOPK_;    // 12288

// ---------------- tiling ----------------
constexpr int BM     = 128;
constexpr int BN_UP  = 128;
constexpr int BND    = 128;
constexpr int BK     = 32;             // K per stage (2 mma k-steps of 16)
constexpr int ASTG   = 3;              // A cp.async stages
constexpr int BSTG   = 2;              // B fp16 smem stages (STS just-in-time)
constexpr int BKP    = BK    + 8;      // 40 halves
constexpr int BNPU   = BN_UP + 8;      // 136 halves
constexpr int BNDP   = BND   + 8;      // 136 halves
constexpr int HROWS  = NPAIR + NE_ * BM + 2 * T_;   // 18,432 padded rows

// smem: pipeline vs epilogue-patch, take max
constexpr int UP_PIPE_B   = (ASTG * BM * BKP + 2 * BSTG * BK * BNPU) * 2;  //  65,536
constexpr int UP_FUSE_B   = 2 * BM * 132 * 4;                              // 135,168
constexpr int UP_SMEM_B   = (UP_PIPE_B > UP_FUSE_B) ? UP_PIPE_B : UP_FUSE_B;
constexpr int DOWN_PIPE_B = (ASTG * BM * BKP + BSTG * BK * BNDP) * 2;      //  48,128
constexpr int DOWN_FUSE_B = BM * 132 * 4;                                  //  67,584
constexpr int DOWN_SMEM_B = (DOWN_PIPE_B > DOWN_FUSE_B) ? DOWN_PIPE_B : DOWN_FUSE_B;
constexpr int FP_ST       = 132;

// ---------------- device scratch (static, no allocation) ----------------
__device__ int    g_is64;
__device__ int    g_cnt[NE2];
__device__ int    g_offpad[NE2 + 1];
__device__ int    g_list[NE_ * NPAIR];
__device__ __half g_Xh  [(size_t)T_ * DIM_];
__device__ __half g_Hh  [(size_t)HROWS * INTER_];
__device__ float  g_Yb  [(size_t)T_ * NSLOT * DIM_];

// ---------------- cp.async helpers ----------------
__device__ __forceinline__ void cpa16(__half* smem, const __half* g) {
    unsigned saddr = (unsigned)__cvta_generic_to_shared(smem);
    asm volatile("cp.async.cg.shared.global [%0], [%1], 16;" :: "r"(saddr), "l"(g));
}
#define CP_COMMIT()  asm volatile("cp.async.commit_group;")
#define CP_WAIT(n)   asm volatile("cp.async.wait_group %0;" :: "n"(n))

// ---------------- fp32 -> fp16 conversion (X only now) ----------------
__global__ void __launch_bounds__(256, 4) cvt_kernel(const float* __restrict__ s,
                                                     __half* __restrict__ d, int n) {
    int i = (blockIdx.x * 256 + threadIdx.x) * 8;
    if (i >= n) return;
    float4 a = *(const float4*)(s + i);
    float4 b = *(const float4*)(s + i + 4);
    __half2 h0 = __floats2half2_rn(a.x, a.y), h1 = __floats2half2_rn(a.z, a.w);
    __half2 h2 = __floats2half2_rn(b.x, b.y), h3 = __floats2half2_rn(b.z, b.w);
    uint4 o;
    o.x = *reinterpret_cast<unsigned*>(&h0);
    o.y = *reinterpret_cast<unsigned*>(&h1);
    o.z = *reinterpret_cast<unsigned*>(&h2);
    o.w = *reinterpret_cast<unsigned*>(&h3);
    *reinterpret_cast<uint4*>(d + i) = o;
}

// ---------------- dtype probe (int64 vs int32 indices) ----------------
__global__ void detect_kernel(const int* __restrict__ idx32) {
    if (threadIdx.x == 0) {
        int a = 0;
        #pragma unroll 1
        for (int i = 0; i < 128; i++) a |= idx32[2 * i + 1];
        g_is64 = (a == 0) ? 1 : 0;
    }
}

// ---------------- deterministic per-expert pair lists ----------------
__global__ void build_lists(const int* __restrict__ idx32) {
    const int e = blockIdx.x;
    const bool is64 = (g_is64 != 0);
    __shared__ int wsum[8];
    __shared__ int sbase;
    const int tid = threadIdx.x, lane = tid & 31, w = tid >> 5;
    if (tid == 0) sbase = 0;
    __syncthreads();
    for (int st = 0; st < NPAIR; st += 256) {
        int p = st + tid;
        int v = is64 ? idx32[2 * p] : idx32[p];
        bool m = (v == e);
        unsigned bal = __ballot_sync(0xffffffffu, m);
        int within = __popc(bal & ((1u << lane) - 1u));
        if (lane == 0) wsum[w] = __popc(bal);
        __syncthreads();
        int off = sbase;
        for (int i = 0; i < w; i++) off += wsum[i];
        if (m) g_list[e * NPAIR + off + within] = p;
        __syncthreads();
        if (tid == 0) {
            int tot = 0;
            for (int i = 0; i < 8; i++) tot += wsum[i];
            sbase += tot;
        }
        __syncthreads();
    }
    if (tid == 0) g_cnt[e] = sbase;
}

__global__ void prefix_kernel() {
    if (threadIdx.x == 0) {
        g_cnt[16] = T_;
        g_cnt[17] = T_;
        int off = 0;
        for (int e = 0; e < NE2; e++) {
            g_offpad[e] = off;
            off += ((g_cnt[e] + BM - 1) / BM) * BM;
        }
        g_offpad[NE2] = off;
    }
}

// ---------------- wmma types (fp16 in, fp32 accum) ----------------
typedef wmma::fragment<wmma::matrix_a, 16, 16, 16, __half, wmma::row_major> FA;
typedef wmma::fragment<wmma::matrix_b, 16, 16, 16, __half, wmma::row_major> FB;
typedef wmma::fragment<wmma::accumulator, 16, 16, 16, float> FC;

// =====================================================================
// up kernel: H[rows] = silu(A@B1) * (A@B3).  256 threads, 8 warps.
// A (X, fp16) via cp.async, 3 stages.  B (W1/W3, fp32) via LDG one
// iteration ahead -> convert -> STS into 2-stage fp16 smem ring.
// e<16: routed (A gathered, B = W1/W3[e], ldB=INTER).
// e>=16: shared pseudo-expert, B = Ws1/Ws3 column slice, ldB=SINTER.
// =====================================================================
__global__ void __launch_bounds__(256, 1)
up_kernel(const float* __restrict__ W1g, const float* __restrict__ W3g,
          const float* __restrict__ Ws1g, const float* __restrict__ Ws3g)
{
    constexpr int KT = DIM_ / BK;     // 64
    const int e = blockIdx.z;
    const int cnt = g_cnt[e];
    if ((int)blockIdx.y * BM >= cnt) return;
    const int hbase = g_offpad[e] + blockIdx.y * BM;
    const bool routed = (e < NE_);

    const float* B1;
    const float* B3;
    size_t ldB;
    if (routed) {
        B1 = W1g + (size_t)e * DIM_ * INTER_;
        B3 = W3g + (size_t)e * DIM_ * INTER_;
        ldB = INTER_;
    } else {
        B1 = Ws1g + (size_t)(e - NE_) * INTER_;
        B3 = Ws3g + (size_t)(e - NE_) * INTER_;
        ldB = SINTER_;
    }
    const int n0 = blockIdx.x * BN_UP;

    extern __shared__ __half sm[];
    __half* sA  = sm;                         // [ASTG][BM][BKP]
    __half* sB1 = sm + ASTG * BM * BKP;       // [BSTG][BK][BNPU]
    __half* sB3 = sB1 + BSTG * BK * BNPU;

    const int tid  = threadIdx.x;
    const int warp = tid >> 5;
    const int grp  = warp >> 2;        // 0: W1, 1: W3
    const int wl   = warp & 3;
    const int wm   = wl & 1;           // 2 warps in M (64 rows)
    const int wn   = wl >> 1;          // 2 warps in N (64 cols)

    // ---- A chunks: 128x32 halves = 512 chunks of 8; 2 per thread
    int tokA[2], arr[2], ac8[2];
    #pragma unroll
    for (int i = 0; i < 2; i++) {
        int id  = tid + 256 * i;
        arr[i]  = id >> 2;
        ac8[i]  = (id & 3) * 8;
        int row = blockIdx.y * BM + arr[i];
        if (routed) tokA[i] = (row < cnt) ? (g_list[e * NPAIR + row] / TOPK_) : 0;
        else        tokA[i] = (row < cnt) ? row : 0;
    }
    auto copyA = [&](int kt, int st) {
        const int k0 = kt * BK;
        #pragma unroll
        for (int i = 0; i < 2; i++)
            cpa16(&sA[(st * BM + arr[i]) * BKP + ac8[i]],
                  g_Xh + (size_t)tokA[i] * DIM_ + k0 + ac8[i]);
    };

    // ---- B chunks: per matrix 32x128 fp32 = 1024 float4; 4 per thread
    int brr[4], bc4[4];
    #pragma unroll
    for (int i = 0; i < 4; i++) {
        int id = tid + 256 * i;
        brr[i] = id >> 5;
        bc4[i] = (id & 31) * 4;
    }
    float4 r1[4], r3[4];
    auto ldgB = [&](int kt) {
        const int k0 = kt * BK;
        #pragma unroll
        for (int i = 0; i < 4; i++) {
            r1[i] = *(const float4*)(B1 + (size_t)(k0 + brr[i]) * ldB + n0 + bc4[i]);
            r3[i] = *(const float4*)(B3 + (size_t)(k0 + brr[i]) * ldB + n0 + bc4[i]);
        }
    };
    auto stsB = [&](int st) {
        #pragma unroll
        for (int i = 0; i < 4; i++) {
            __half2 a0 = __floats2half2_rn(r1[i].x, r1[i].y);
            __half2 a1 = __floats2half2_rn(r1[i].z, r1[i].w);
            uint2 v1;
            v1.x = *reinterpret_cast<unsigned*>(&a0);
            v1.y = *reinterpret_cast<unsigned*>(&a1);
            *reinterpret_cast<uint2*>(&sB1[(st * BK + brr[i]) * BNPU + bc4[i]]) = v1;
            __half2 b0 = __floats2half2_rn(r3[i].x, r3[i].y);
            __half2 b1 = __floats2half2_rn(r3[i].z, r3[i].w);
            uint2 v3;
            v3.x = *reinterpret_cast<unsigned*>(&b0);
            v3.y = *reinterpret_cast<unsigned*>(&b1);
            *reinterpret_cast<uint2*>(&sB3[(st * BK + brr[i]) * BNPU + bc4[i]]) = v3;
        }
    };

    FC acc[4][4];
    #pragma unroll
    for (int mi = 0; mi < 4; mi++)
        #pragma unroll
        for (int ni = 0; ni < 4; ni++) wmma::fill_fragment(acc[mi][ni], 0.f);

    const __half* sBg = grp ? sB3 : sB1;

    // prologue
    copyA(0, 0); CP_COMMIT();
    copyA(1, 1); CP_COMMIT();
    ldgB(0); stsB(0);
    CP_WAIT(1);
    __syncthreads();

    for (int kt = 0; kt < KT; kt++) {
        if (kt + 1 < KT) ldgB(kt + 1);
        if (kt + 2 < KT) copyA(kt + 2, (kt + 2) % ASTG);
        CP_COMMIT();
        const int sa = kt % ASTG;
        const int sb = kt % BSTG;
        #pragma unroll
        for (int kk = 0; kk < BK; kk += 16) {
            FA fa[4];
            FB fb[4];
            #pragma unroll
            for (int mi = 0; mi < 4; mi++)
                wmma::load_matrix_sync(fa[mi], &sA[(sa * BM + wm * 64 + mi * 16) * BKP + kk], BKP);
            #pragma unroll
            for (int ni = 0; ni < 4; ni++)
                wmma::load_matrix_sync(fb[ni], &sBg[(sb * BK + kk) * BNPU + wn * 64 + ni * 16], BNPU);
            #pragma unroll
            for (int mi = 0; mi < 4; mi++)
                #pragma unroll
                for (int ni = 0; ni < 4; ni++)
                    wmma::mma_sync(acc[mi][ni], fa[mi], fb[ni], acc[mi][ni]);
        }
        if (kt + 1 < KT) stsB((kt + 1) % BSTG);
        CP_WAIT(1);
        __syncthreads();
    }

    // ---- epilogue: dump both groups' accs to smem floats, fuse, store fp16 H
    CP_WAIT(0);
    __syncthreads();
    float* sF  = (float*)sm;                  // [2][BM][FP_ST]
    float* sFm = sF + grp * (BM * FP_ST);
    #pragma unroll
    for (int mi = 0; mi < 4; mi++)
        #pragma unroll
        for (int ni = 0; ni < 4; ni++)
            wmma::store_matrix_sync(&sFm[(wm * 64 + mi * 16) * FP_ST + wn * 64 + ni * 16],
                                    acc[mi][ni], FP_ST, wmma::mem_row_major);
    __syncthreads();

    {
        const int row = tid >> 1;
        const int seg = (tid & 1) * 64;
        const float* p1 = &sF[row * FP_ST + seg];
        const float* p3 = p1 + BM * FP_ST;
        __half* dst = g_Hh + (size_t)(hbase + row) * INTER_ + n0 + seg;
        #pragma unroll
        for (int c = 0; c < 64; c += 16) {
            __align__(16) __half hbuf[16];
            #pragma unroll
            for (int j = 0; j < 16; j++) {
                float u = p1[c + j];
                float s = u / (1.f + __expf(-u));
                hbuf[j] = __float2half_rn(s * p3[c + j]);
            }
            *(uint4*)(dst + c)     = *(uint4*)(hbuf);
            *(uint4*)(dst + c + 8) = *(uint4*)(hbuf + 8);
        }
    }
}

// =====================================================================
// down kernel: Y = H @ B.  128 threads, 4 warps (2x2 of 64x64), 2 CTAs/SM.
// A (H, fp16) via cp.async 3 stages; B (W2/Ws2, fp32) via LDG+convert+STS.
// e<16: scatter to slot t*8+k scaled by routing weight.
// e>=16: B = Ws2 rows [h*INTER,(h+1)*INTER), slot t*8+6+h, w=1.
// =====================================================================
__global__ void __launch_bounds__(128, 2)
down_kernel(const float* __restrict__ W2g, const float* __restrict__ Ws2g,
            const float* __restrict__ wts)
{
    constexpr int KT = INTER_ / BK;   // 44
    const int e = blockIdx.z;
    const int cnt = g_cnt[e];
    if ((int)blockIdx.y * BM >= cnt) return;
    const int abase = g_offpad[e] + blockIdx.y * BM;
    const bool routed = (e < NE_);

    const float* Bh = routed ? (W2g + (size_t)e * INTER_ * DIM_)
                             : (Ws2g + (size_t)(e - NE_) * INTER_ * DIM_);
    const int n0 = blockIdx.x * BND;

    extern __shared__ __half sm[];
    __half* sA = sm;                          // [ASTG][BM][BKP]
    __half* sB = sm + ASTG * BM * BKP;        // [BSTG][BK][BNDP]

    const int tid  = threadIdx.x;
    const int warp = tid >> 5;
    const int wm   = warp & 1;
    const int wn   = warp >> 1;

    // A chunks: 512 chunks of 8 halves; 4 per thread
    auto copyA = [&](int kt, int st) {
        const int k0 = kt * BK;
        #pragma unroll
        for (int i = 0; i < 4; i++) {
            int id = tid + 128 * i;
            int r  = id >> 2;
            int c8 = (id & 3) * 8;
            cpa16(&sA[(st * BM + r) * BKP + c8],
                  g_Hh + (size_t)(abase + r) * INTER_ + k0 + c8);
        }
    };

    // B chunks: 32x128 fp32 = 1024 float4; 8 per thread
    float4 rB[8];
    auto ldgB = [&](int kt) {
        const int k0 = kt * BK;
        #pragma unroll
        for (int i = 0; i < 8; i++) {
            int id = tid + 128 * i;
            int r  = id >> 5;
            int c4 = (id & 31) * 4;
            rB[i] = *(const float4*)(Bh + (size_t)(k0 + r) * DIM_ + n0 + c4);
        }
    };
    auto stsB = [&](int st) {
        #pragma unroll
        for (int i = 0; i < 8; i++) {
            int id = tid + 128 * i;
            int r  = id >> 5;
            int c4 = (id & 31) * 4;
            __half2 a0 = __floats2half2_rn(rB[i].x, rB[i].y);
            __half2 a1 = __floats2half2_rn(rB[i].z, rB[i].w);
            uint2 v;
            v.x = *reinterpret_cast<unsigned*>(&a0);
            v.y = *reinterpret_cast<unsigned*>(&a1);
            *reinterpret_cast<uint2*>(&sB[(st * BK + r) * BNDP + c4]) = v;
        }
    };

    FC acc[4][4];
    #pragma unroll
    for (int mi = 0; mi < 4; mi++)
        #pragma unroll
        for (int ni = 0; ni < 4; ni++) wmma::fill_fragment(acc[mi][ni], 0.f);

    copyA(0, 0); CP_COMMIT();
    copyA(1, 1); CP_COMMIT();
    ldgB(0); stsB(0);
    CP_WAIT(1);
    __syncthreads();

    for (int kt = 0; kt < KT; kt++) {
        if (kt + 1 < KT) ldgB(kt + 1);
        if (kt + 2 < KT) copyA(kt + 2, (kt + 2) % ASTG);
        CP_COMMIT();
        const int sa = kt % ASTG;
        const int sb = kt % BSTG;
        #pragma unroll
        for (int kk = 0; kk < BK; kk += 16) {
            FA fa[4];
            FB fb[4];
            #pragma unroll
            for (int mi = 0; mi < 4; mi++)
                wmma::load_matrix_sync(fa[mi], &sA[(sa * BM + wm * 64 + mi * 16) * BKP + kk], BKP);
            #pragma unroll
            for (int ni = 0; ni < 4; ni++)
                wmma::load_matrix_sync(fb[ni], &sB[(sb * BK + kk) * BNDP + wn * 64 + ni * 16], BNDP);
            #pragma unroll
            for (int mi = 0; mi < 4; mi++)
                #pragma unroll
                for (int ni = 0; ni < 4; ni++)
                    wmma::mma_sync(acc[mi][ni], fa[mi], fb[ni], acc[mi][ni]);
        }
        if (kt + 1 < KT) stsB((kt + 1) % BSTG);
        CP_WAIT(1);
        __syncthreads();
    }

    CP_WAIT(0);
    __syncthreads();
    float* sF = (float*)sm;                   // [BM][FP_ST]
    #pragma unroll
    for (int mi = 0; mi < 4; mi++)
        #pragma unroll
        for (int ni = 0; ni < 4; ni++)
            wmma::store_matrix_sync(&sF[(wm * 64 + mi * 16) * FP_ST + wn * 64 + ni * 16],
                                    acc[mi][ni], FP_ST, wmma::mem_row_major);
    __syncthreads();

    {
        const int row = tid;                  // one row per thread
        const float* src = &sF[row * FP_ST];
        const int gslot = blockIdx.y * BM + row;
        if (gslot < cnt) {
            int slot;
            float w;
            if (routed) {
                int p = g_list[e * NPAIR + gslot];
                int t = p / TOPK_;
                int k = p - t * TOPK_;
                slot = t * NSLOT + k;
                w = wts[p];
            } else {
                slot = gslot * NSLOT + TOPK_ + (e - NE_);
                w = 1.f;
            }
            float* dst = g_Yb + (size_t)slot * DIM_ + n0;
            #pragma unroll
            for (int j = 0; j < 128; j += 4) {
                float4 v = *(const float4*)(src + j);
                v.x *= w; v.y *= w; v.z *= w; v.w *= w;
                *(float4*)(dst + j) = v;
            }
        }
    }
}

// ---------------- final reduction: out[t] = sum over 8 slots ----------------
__global__ void __launch_bounds__(256, 1) reduce_kernel(float* __restrict__ out) {
    int i = blockIdx.x * 256 + threadIdx.x;
    const int row4 = DIM_ / 4;
    int t  = i / row4;
    int c4 = i % row4;
    const float* base = g_Yb + (size_t)t * NSLOT * DIM_ + c4 * 4;
    float4 a = *(const float4*)(base);
    #pragma unroll
    for (int k = 1; k < NSLOT; k++) {
        const float4 v = *(const float4*)(base + (size_t)k * DIM_);
        a.x += v.x; a.y += v.y; a.z += v.z; a.w += v.w;
    }
    ((float4*)out)[i] = a;
}

// ---------------- launch (single stream) ----------------
extern "C" void kernel_launch(void* const* d_in, const int* in_sizes, int n_in,
                              void* d_out, int out_size) {
    const float* x   = (const float*)d_in[0];
    const float* wts = (const float*)d_in[1];
    const int*   idx = (const int*)  d_in[2];
    const float* W1  = (const float*)d_in[3];
    const float* W3  = (const float*)d_in[4];
    const float* W2  = (const float*)d_in[5];
    const float* Ws1 = (const float*)d_in[6];
    const float* Ws3 = (const float*)d_in[7];
    const float* Ws2 = (const float*)d_in[8];
    float* out = (float*)d_out;

    cudaFuncSetAttribute(up_kernel,   cudaFuncAttributeMaxDynamicSharedMemorySize, UP_SMEM_B);
    cudaFuncSetAttribute(down_kernel, cudaFuncAttributeMaxDynamicSharedMemorySize, DOWN_SMEM_B);

    void* pXh;
    cudaGetSymbolAddress(&pXh, g_Xh);

    // only X needs pre-conversion now (high reuse); weights convert in-GEMM
    {
        long long n = (long long)T_ * DIM_;
        cvt_kernel<<<(int)((n + 2047) / 2048), 256>>>(x, (__half*)pXh, (int)n);
    }

    detect_kernel<<<1, 32>>>(idx);
    build_lists<<<NE_, 256>>>(idx);
    prefix_kernel<<<1, 32>>>();

    // unified up: routed experts (z<16) + shared pseudo-experts (z=16,17)
    up_kernel<<<dim3(INTER_ / BN_UP, NPAIR / BM, NE2), 256, UP_SMEM_B>>>(W1, W3, Ws1, Ws3);
    // unified down: K = INTER for all
    down_kernel<<<dim3(DIM_ / BND, NPAIR / BM, NE2), 128, DOWN_SMEM_B>>>(W2, Ws2, wts);
    // out[t] = sum over 8 slots
    reduce_kernel<<<(T_ * DIM_ / 4) / 256, 256>>>(out);
}

// round 17
// speedup vs baseline: 1.0331x; 1.0128x over previous
#include <cuda_runtime.h>
#include <cuda_fp16.h>
#include <mma.h>
#include <cstdint>

using namespace nvcuda;

// ---------------- problem constants ----------------
constexpr int T_      = 2048;
constexpr int DIM_    = 2048;
constexpr int INTER_  = 1408;
constexpr int SINTER_ = 2816;          // == 2 * INTER_
constexpr int NE_     = 16;
constexpr int NE2     = 18;            // 16 routed + 2 shared pseudo-experts
constexpr int TOPK_   = 6;
constexpr int NSLOT   = 8;             // 6 routed + 2 shared
constexpr int NPAIR   = T_ * TOPK_;    // 12288

// ---------------- tiling ----------------
constexpr int BM     = 128;
constexpr int BN_UP  = 128;
constexpr int BND    = 128;
constexpr int BK     = 32;             // K per stage (2 mma k-steps of 16)
constexpr int ASTG   = 3;              // up: A cp.async stages
constexpr int BSTG   = 2;              // up: B fp16 smem stages (LDG+cvt+STS)
constexpr int DSTG   = 4;              // down: cp.async stages (both operands fp16)
constexpr int BKP    = BK    + 8;      // 40 halves
constexpr int BNPU   = BN_UP + 8;      // 136 halves
constexpr int BNDP   = BND   + 8;      // 136 halves
constexpr int HROWS  = NPAIR + NE_ * BM + 2 * T_;   // 18,432 padded rows

// smem: pipeline vs epilogue-patch, take max
constexpr int UP_PIPE_B   = (ASTG * BM * BKP + 2 * BSTG * BK * BNPU) * 2;  //  65,536
constexpr int UP_FUSE_B   = 2 * BM * 132 * 4;                              // 135,168
constexpr int UP_SMEM_B   = (UP_PIPE_B > UP_FUSE_B) ? UP_PIPE_B : UP_FUSE_B;
constexpr int DOWN_PIPE_B = (DSTG * BM * BKP + DSTG * BK * BNDP) * 2;      //  75,776
constexpr int DOWN_FUSE_B = BM * 132 * 4;                                  //  67,584
constexpr int DOWN_SMEM_B = (DOWN_PIPE_B > DOWN_FUSE_B) ? DOWN_PIPE_B : DOWN_FUSE_B;
constexpr int FP_ST       = 132;

// ---------------- device scratch (static, no allocation) ----------------
__device__ int    g_is64;
__device__ int    g_cnt[NE2];
__device__ int    g_offpad[NE2 + 1];
__device__ int    g_list[NE_ * NPAIR];
__device__ __half g_W2h [(size_t)NE_ * INTER_ * DIM_];
__device__ __half g_Ws2h[(size_t)SINTER_ * DIM_];
__device__ __half g_Xh  [(size_t)T_ * DIM_];
__device__ __half g_Hh  [(size_t)HROWS * INTER_];
__device__ float  g_Yb  [(size_t)T_ * NSLOT * DIM_];

// ---------------- cp.async helpers ----------------
__device__ __forceinline__ void cpa16(__half* smem, const __half* g) {
    unsigned saddr = (unsigned)__cvta_generic_to_shared(smem);
    asm volatile("cp.async.cg.shared.global [%0], [%1], 16;" :: "r"(saddr), "l"(g));
}
#define CP_COMMIT()  asm volatile("cp.async.commit_group;")
#define CP_WAIT(n)   asm volatile("cp.async.wait_group %0;" :: "n"(n))

// ---------------- fp32 -> fp16 8-wide convert helper ----------------
__device__ __forceinline__ void cvt8(const float* __restrict__ s, __half* __restrict__ d) {
    float4 a = *(const float4*)(s);
    float4 b = *(const float4*)(s + 4);
    __half2 h0 = __floats2half2_rn(a.x, a.y), h1 = __floats2half2_rn(a.z, a.w);
    __half2 h2 = __floats2half2_rn(b.x, b.y), h3 = __floats2half2_rn(b.z, b.w);
    uint4 o;
    o.x = *reinterpret_cast<unsigned*>(&h0);
    o.y = *reinterpret_cast<unsigned*>(&h1);
    o.z = *reinterpret_cast<unsigned*>(&h2);
    o.w = *reinterpret_cast<unsigned*>(&h3);
    *reinterpret_cast<uint4*>(d) = o;
}

// ---------------- fp32 -> fp16 conversion (X only) ----------------
__global__ void __launch_bounds__(256, 4) cvt_kernel(const float* __restrict__ s,
                                                     __half* __restrict__ d, int n) {
    int i = (blockIdx.x * 256 + threadIdx.x) * 8;
    if (i >= n) return;
    cvt8(s + i, d + i);
}

// ---------------- dtype probe (int64 vs int32 indices) ----------------
__global__ void detect_kernel(const int* __restrict__ idx32) {
    if (threadIdx.x == 0) {
        int a = 0;
        #pragma unroll 1
        for (int i = 0; i < 128; i++) a |= idx32[2 * i + 1];
        g_is64 = (a == 0) ? 1 : 0;
    }
}

// ---------------- deterministic per-expert pair lists ----------------
__global__ void build_lists(const int* __restrict__ idx32) {
    const int e = blockIdx.x;
    const bool is64 = (g_is64 != 0);
    __shared__ int wsum[8];
    __shared__ int sbase;
    const int tid = threadIdx.x, lane = tid & 31, w = tid >> 5;
    if (tid == 0) sbase = 0;
    __syncthreads();
    for (int st = 0; st < NPAIR; st += 256) {
        int p = st + tid;
        int v = is64 ? idx32[2 * p] : idx32[p];
        bool m = (v == e);
        unsigned bal = __ballot_sync(0xffffffffu, m);
        int within = __popc(bal & ((1u << lane) - 1u));
        if (lane == 0) wsum[w] = __popc(bal);
        __syncthreads();
        int off = sbase;
        for (int i = 0; i < w; i++) off += wsum[i];
        if (m) g_list[e * NPAIR + off + within] = p;
        __syncthreads();
        if (tid == 0) {
            int tot = 0;
            for (int i = 0; i < 8; i++) tot += wsum[i];
            sbase += tot;
        }
        __syncthreads();
    }
    if (tid == 0) g_cnt[e] = sbase;
}

__global__ void prefix_kernel() {
    if (threadIdx.x == 0) {
        g_cnt[16] = T_;
        g_cnt[17] = T_;
        int off = 0;
        for (int e = 0; e < NE2; e++) {
            g_offpad[e] = off;
            off += ((g_cnt[e] + BM - 1) / BM) * BM;
        }
        g_offpad[NE2] = off;
    }
}

// ---------------- wmma types (fp16 in, fp32 accum) ----------------
typedef wmma::fragment<wmma::matrix_a, 16, 16, 16, __half, wmma::row_major> FA;
typedef wmma::fragment<wmma::matrix_b, 16, 16, 16, __half, wmma::row_major> FB;
typedef wmma::fragment<wmma::accumulator, 16, 16, 16, float> FC;

// =====================================================================
// up kernel: H[rows] = silu(A@B1) * (A@B3).  256 threads, 8 warps.
// z < 18:  GEMM blocks (A fp16 cp.async; B fp32 LDG+cvt+STS, 2-stage).
// z == 18: auxiliary converter blocks — convert W2/Ws2 to fp16 for the
//          down kernel, overlapped with the GEMM blocks of this launch.
// =====================================================================
__global__ void __launch_bounds__(256, 1)
up_kernel(const float* __restrict__ W1g, const float* __restrict__ W3g,
          const float* __restrict__ Ws1g, const float* __restrict__ Ws3g,
          const float* __restrict__ W2g, const float* __restrict__ Ws2g)
{
    constexpr int KT = DIM_ / BK;     // 64
    const int e = blockIdx.z;

    // ---- auxiliary conversion slice (overlaps GEMM blocks) ----
    if (e == NE2) {
        if (blockIdx.x != 0) return;
        const long long nW2  = (long long)NE_ * INTER_ * DIM_;   // 46,137,344
        const long long nWs2 = (long long)SINTER_ * DIM_;        //  5,767,168
        const long long NT   = 96LL * 256LL;
        long long g = (long long)blockIdx.y * 256 + threadIdx.x;
        for (long long i = g * 8; i < nW2; i += NT * 8)
            cvt8(W2g + i, g_W2h + i);
        for (long long i = g * 8; i < nWs2; i += NT * 8)
            cvt8(Ws2g + i, g_Ws2h + i);
        return;
    }

    const int cnt = g_cnt[e];
    if ((int)blockIdx.y * BM >= cnt) return;
    const int hbase = g_offpad[e] + blockIdx.y * BM;
    const bool routed = (e < NE_);

    const float* B1;
    const float* B3;
    size_t ldB;
    if (routed) {
        B1 = W1g + (size_t)e * DIM_ * INTER_;
        B3 = W3g + (size_t)e * DIM_ * INTER_;
        ldB = INTER_;
    } else {
        B1 = Ws1g + (size_t)(e - NE_) * INTER_;
        B3 = Ws3g + (size_t)(e - NE_) * INTER_;
        ldB = SINTER_;
    }
    const int n0 = blockIdx.x * BN_UP;

    extern __shared__ __half sm[];
    __half* sA  = sm;                         // [ASTG][BM][BKP]
    __half* sB1 = sm + ASTG * BM * BKP;       // [BSTG][BK][BNPU]
    __half* sB3 = sB1 + BSTG * BK * BNPU;

    const int tid  = threadIdx.x;
    const int warp = tid >> 5;
    const int grp  = warp >> 2;        // 0: W1, 1: W3
    const int wl   = warp & 3;
    const int wm   = wl & 1;           // 2 warps in M (64 rows)
    const int wn   = wl >> 1;          // 2 warps in N (64 cols)

    // ---- A chunks: 128x32 halves = 512 chunks of 8; 2 per thread
    int tokA[2], arr[2], ac8[2];
    #pragma unroll
    for (int i = 0; i < 2; i++) {
        int id  = tid + 256 * i;
        arr[i]  = id >> 2;
        ac8[i]  = (id & 3) * 8;
        int row = blockIdx.y * BM + arr[i];
        if (routed) tokA[i] = (row < cnt) ? (g_list[e * NPAIR + row] / TOPK_) : 0;
        else        tokA[i] = (row < cnt) ? row : 0;
    }
    auto copyA = [&](int kt, int st) {
        const int k0 = kt * BK;
        #pragma unroll
        for (int i = 0; i < 2; i++)
            cpa16(&sA[(st * BM + arr[i]) * BKP + ac8[i]],
                  g_Xh + (size_t)tokA[i] * DIM_ + k0 + ac8[i]);
    };

    // ---- B chunks: per matrix 32x128 fp32 = 1024 float4; 4 per thread
    int brr[4], bc4[4];
    #pragma unroll
    for (int i = 0; i < 4; i++) {
        int id = tid + 256 * i;
        brr[i] = id >> 5;
        bc4[i] = (id & 31) * 4;
    }
    float4 r1[4], r3[4];
    auto ldgB = [&](int kt) {
        const int k0 = kt * BK;
        #pragma unroll
        for (int i = 0; i < 4; i++) {
            r1[i] = *(const float4*)(B1 + (size_t)(k0 + brr[i]) * ldB + n0 + bc4[i]);
            r3[i] = *(const float4*)(B3 + (size_t)(k0 + brr[i]) * ldB + n0 + bc4[i]);
        }
    };
    auto stsB = [&](int st) {
        #pragma unroll
        for (int i = 0; i < 4; i++) {
            __half2 a0 = __floats2half2_rn(r1[i].x, r1[i].y);
            __half2 a1 = __floats2half2_rn(r1[i].z, r1[i].w);
            uint2 v1;
            v1.x = *reinterpret_cast<unsigned*>(&a0);
            v1.y = *reinterpret_cast<unsigned*>(&a1);
            *reinterpret_cast<uint2*>(&sB1[(st * BK + brr[i]) * BNPU + bc4[i]]) = v1;
            __half2 b0 = __floats2half2_rn(r3[i].x, r3[i].y);
            __half2 b1 = __floats2half2_rn(r3[i].z, r3[i].w);
            uint2 v3;
            v3.x = *reinterpret_cast<unsigned*>(&b0);
            v3.y = *reinterpret_cast<unsigned*>(&b1);
            *reinterpret_cast<uint2*>(&sB3[(st * BK + brr[i]) * BNPU + bc4[i]]) = v3;
        }
    };

    FC acc[4][4];
    #pragma unroll
    for (int mi = 0; mi < 4; mi++)
        #pragma unroll
        for (int ni = 0; ni < 4; ni++) wmma::fill_fragment(acc[mi][ni], 0.f);

    const __half* sBg = grp ? sB3 : sB1;

    // prologue
    copyA(0, 0); CP_COMMIT();
    copyA(1, 1); CP_COMMIT();
    ldgB(0); stsB(0);
    CP_WAIT(1);
    __syncthreads();

    for (int kt = 0; kt < KT; kt++) {
        if (kt + 1 < KT) ldgB(kt + 1);
        if (kt + 2 < KT) copyA(kt + 2, (kt + 2) % ASTG);
        CP_COMMIT();
        const int sa = kt % ASTG;
        const int sb = kt % BSTG;
        #pragma unroll
        for (int kk = 0; kk < BK; kk += 16) {
            FA fa[4];
            FB fb[4];
            #pragma unroll
            for (int mi = 0; mi < 4; mi++)
                wmma::load_matrix_sync(fa[mi], &sA[(sa * BM + wm * 64 + mi * 16) * BKP + kk], BKP);
            #pragma unroll
            for (int ni = 0; ni < 4; ni++)
                wmma::load_matrix_sync(fb[ni], &sBg[(sb * BK + kk) * BNPU + wn * 64 + ni * 16], BNPU);
            #pragma unroll
            for (int mi = 0; mi < 4; mi++)
                #pragma unroll
                for (int ni = 0; ni < 4; ni++)
                    wmma::mma_sync(acc[mi][ni], fa[mi], fb[ni], acc[mi][ni]);
        }
        if (kt + 1 < KT) stsB((kt + 1) % BSTG);
        CP_WAIT(1);
        __syncthreads();
    }

    // ---- epilogue: dump both groups' accs to smem floats, fuse, store fp16 H
    CP_WAIT(0);
    __syncthreads();
    float* sF  = (float*)sm;                  // [2][BM][FP_ST]
    float* sFm = sF + grp * (BM * FP_ST);
    #pragma unroll
    for (int mi = 0; mi < 4; mi++)
        #pragma unroll
        for (int ni = 0; ni < 4; ni++)
            wmma::store_matrix_sync(&sFm[(wm * 64 + mi * 16) * FP_ST + wn * 64 + ni * 16],
                                    acc[mi][ni], FP_ST, wmma::mem_row_major);
    __syncthreads();

    {
        const int row = tid >> 1;
        const int seg = (tid & 1) * 64;
        const float* p1 = &sF[row * FP_ST + seg];
        const float* p3 = p1 + BM * FP_ST;
        __half* dst = g_Hh + (size_t)(hbase + row) * INTER_ + n0 + seg;
        #pragma unroll
        for (int c = 0; c < 64; c += 16) {
            __align__(16) __half hbuf[16];
            #pragma unroll
            for (int j = 0; j < 16; j++) {
                float u = p1[c + j];
                float s = u / (1.f + __expf(-u));
                hbuf[j] = __float2half_rn(s * p3[c + j]);
            }
            *(uint4*)(dst + c)     = *(uint4*)(hbuf);
            *(uint4*)(dst + c + 8) = *(uint4*)(hbuf + 8);
        }
    }
}

// =====================================================================
// down kernel: Y = H @ B.  128 threads, 4 warps (2x2 of 64x64), 2 CTAs/SM.
// Both operands fp16 via cp.async, 4 stages (B pre-converted by up's aux
// blocks).  e<16: scatter to slot t*8+k scaled by routing weight.
// e>=16: B = Ws2 rows [h*INTER,(h+1)*INTER), slot t*8+6+h, w=1.
// =====================================================================
__global__ void __launch_bounds__(128, 2)
down_kernel(const float* __restrict__ wts)
{
    constexpr int KT = INTER_ / BK;   // 44
    const int e = blockIdx.z;
    const int cnt = g_cnt[e];
    if ((int)blockIdx.y * BM >= cnt) return;
    const int abase = g_offpad[e] + blockIdx.y * BM;
    const bool routed = (e < NE_);

    const __half* Bh = routed ? (g_W2h + (size_t)e * INTER_ * DIM_)
                              : (g_Ws2h + (size_t)(e - NE_) * INTER_ * DIM_);
    const int n0 = blockIdx.x * BND;

    extern __shared__ __half sm[];
    __half* sA = sm;                                // [DSTG][BM][BKP]
    __half* sB = sm + DSTG * BM * BKP;              // [DSTG][BK][BNDP]

    const int tid  = threadIdx.x;
    const int warp = tid >> 5;
    const int wm   = warp & 1;
    const int wn   = warp >> 1;

    auto copy_stage = [&](int kt, int st) {
        const int k0 = kt * BK;
        #pragma unroll
        for (int i = 0; i < 4; i++) {
            int id = tid + 128 * i;
            int r  = id >> 2;
            int c8 = (id & 3) * 8;
            cpa16(&sA[(st * BM + r) * BKP + c8],
                  g_Hh + (size_t)(abase + r) * INTER_ + k0 + c8);
        }
        #pragma unroll
        for (int i = 0; i < 4; i++) {
            int id = tid + 128 * i;
            int r  = id >> 4;
            int c8 = (id & 15) * 8;
            cpa16(&sB[(st * BK + r) * BNDP + c8],
                  Bh + (size_t)(k0 + r) * DIM_ + n0 + c8);
        }
    };

    FC acc[4][4];
    #pragma unroll
    for (int mi = 0; mi < 4; mi++)
        #pragma unroll
        for (int ni = 0; ni < 4; ni++) wmma::fill_fragment(acc[mi][ni], 0.f);

    #pragma unroll
    for (int s = 0; s < DSTG - 1; s++) { copy_stage(s, s); CP_COMMIT(); }

    for (int kt = 0; kt < KT; kt++) {
        CP_WAIT(DSTG - 2);
        __syncthreads();
        int nk = kt + DSTG - 1;
        if (nk < KT) copy_stage(nk, nk % DSTG);
        CP_COMMIT();
        const int st = kt % DSTG;
        #pragma unroll
        for (int kk = 0; kk < BK; kk += 16) {
            FA fa[4];
            FB fb[4];
            #pragma unroll
            for (int mi = 0; mi < 4; mi++)
                wmma::load_matrix_sync(fa[mi], &sA[(st * BM + wm * 64 + mi * 16) * BKP + kk], BKP);
            #pragma unroll
            for (int ni = 0; ni < 4; ni++)
                wmma::load_matrix_sync(fb[ni], &sB[(st * BK + kk) * BNDP + wn * 64 + ni * 16], BNDP);
            #pragma unroll
            for (int mi = 0; mi < 4; mi++)
                #pragma unroll
                for (int ni = 0; ni < 4; ni++)
                    wmma::mma_sync(acc[mi][ni], fa[mi], fb[ni], acc[mi][ni]);
        }
    }

    CP_WAIT(0);
    __syncthreads();
    float* sF = (float*)sm;                   // [BM][FP_ST]
    #pragma unroll
    for (int mi = 0; mi < 4; mi++)
        #pragma unroll
        for (int ni = 0; ni < 4; ni++)
            wmma::store_matrix_sync(&sF[(wm * 64 + mi * 16) * FP_ST + wn * 64 + ni * 16],
                                    acc[mi][ni], FP_ST, wmma::mem_row_major);
    __syncthreads();

    {
        const int row = tid;                  // one row per thread
        const float* src = &sF[row * FP_ST];
        const int gslot = blockIdx.y * BM + row;
        if (gslot < cnt) {
            int slot;
            float w;
            if (routed) {
                int p = g_list[e * NPAIR + gslot];
                int t = p / TOPK_;
                int k = p - t * TOPK_;
                slot = t * NSLOT + k;
                w = wts[p];
            } else {
                slot = gslot * NSLOT + TOPK_ + (e - NE_);
                w = 1.f;
            }
            float* dst = g_Yb + (size_t)slot * DIM_ + n0;
            #pragma unroll
            for (int j = 0; j < 128; j += 4) {
                float4 v = *(const float4*)(src + j);
                v.x *= w; v.y *= w; v.z *= w; v.w *= w;
                *(float4*)(dst + j) = v;
            }
        }
    }
}

// ---------------- final reduction: out[t] = sum over 8 slots ----------------
__global__ void __launch_bounds__(256, 1) reduce_kernel(float* __restrict__ out) {
    int i = blockIdx.x * 256 + threadIdx.x;
    const int row4 = DIM_ / 4;
    int t  = i / row4;
    int c4 = i % row4;
    const float* base = g_Yb + (size_t)t * NSLOT * DIM_ + c4 * 4;
    float4 a = *(const float4*)(base);
    #pragma unroll
    for (int k = 1; k < NSLOT; k++) {
        const float4 v = *(const float4*)(base + (size_t)k * DIM_);
        a.x += v.x; a.y += v.y; a.z += v.z; a.w += v.w;
    }
    ((float4*)out)[i] = a;
}

// ---------------- launch (single stream) ----------------
extern "C" void kernel_launch(void* const* d_in, const int* in_sizes, int n_in,
                              void* d_out, int out_size) {
    const float* x   = (const float*)d_in[0];
    const float* wts = (const float*)d_in[1];
    const int*   idx = (const int*)  d_in[2];
    const float* W1  = (const float*)d_in[3];
    const float* W3  = (const float*)d_in[4];
    const float* W2  = (const float*)d_in[5];
    const float* Ws1 = (const float*)d_in[6];
    const float* Ws3 = (const float*)d_in[7];
    const float* Ws2 = (const float*)d_in[8];
    float* out = (float*)d_out;

    cudaFuncSetAttribute(up_kernel,   cudaFuncAttributeMaxDynamicSharedMemorySize, UP_SMEM_B);
    cudaFuncSetAttribute(down_kernel, cudaFuncAttributeMaxDynamicSharedMemorySize, DOWN_SMEM_B);

    void* pXh;
    cudaGetSymbolAddress(&pXh, g_Xh);

    // only X needs pre-conversion (high reuse); W1/W3/Ws1/Ws3 convert
    // in-GEMM inside up; W2/Ws2 convert in up's auxiliary blocks.
    {
        long long n = (long long)T_ * DIM_;
        cvt_kernel<<<(int)((n + 2047) / 2048), 256>>>(x, (__half*)pXh, (int)n);
    }

    detect_kernel<<<1, 32>>>(idx);
    build_lists<<<NE_, 256>>>(idx);
    prefix_kernel<<<1, 32>>>();

    // unified up (z<18 GEMM; z==18 aux W2/Ws2 conversion, overlapped)
    up_kernel<<<dim3(INTER_ / BN_UP, NPAIR / BM, NE2 + 1), 256, UP_SMEM_B>>>(
        W1, W3, Ws1, Ws3, W2, Ws2);
    // unified down: K = INTER for all, fp16 B
    down_kernel<<<dim3(DIM_ / BND, NPAIR / BM, NE2), 128, DOWN_SMEM_B>>>(wts);
    // out[t] = sum over 8 slots
    reduce_kernel<<<(T_ * DIM_ / 4) / 256, 256>>>(out);
}